// round 6
// baseline (speedup 1.0000x reference)
#include <cuda_runtime.h>
#include <cstddef>
#include <cstdint>

#define VOCABN 50000
#define DIMN   300
#define HN     100
#define TN     512
#define BN     256
#define OUTN   3
#define G4     400   // 4*H
#define G4P    448   // padded N (7 tiles of 64)
#define KP0    304   // padded K for layer-0 table GEMM (emb K=300)
#define KP1    112   // padded K for xg GEMMs (h K=100)
#define HALF   (BN / 2)

// ---------------- scratch (static device globals; no allocation) ----------------
__device__ float g_table[(size_t)VOCABN * G4];
__device__ float g_xg[(size_t)BN * TN * G4];
__device__ float g_h[(size_t)BN * TN * HN];
__device__ float g_hlast[BN * HN];
__device__ int   g_order[BN];
__device__ float g_w0p[(size_t)G4P * KP0];
__device__ float g_w1p[(size_t)G4P * KP1];
__device__ float g_w2p[(size_t)G4P * KP1];

// ---------------- packed f32x2 helpers ----------------
typedef unsigned long long ull;

__device__ __forceinline__ ull pack2(float x, float y) {
    ull r;
    asm("mov.b64 %0, {%1, %2};" : "=l"(r) : "f"(x), "f"(y));
    return r;
}
__device__ __forceinline__ void unpack2(ull v, float& x, float& y) {
    asm("mov.b64 {%0, %1}, %2;" : "=f"(x), "=f"(y) : "l"(v));
}
__device__ __forceinline__ ull fma2(ull a, ull b, ull c) {
    ull d;
    asm("fma.rn.f32x2 %0, %1, %2, %3;" : "=l"(d) : "l"(a), "l"(b), "l"(c));
    return d;
}

// ---------------- tf32 helpers ----------------
__device__ __forceinline__ uint32_t f2tf(float x) {
    uint32_t r;
    asm("cvt.rna.tf32.f32 %0, %1;" : "=r"(r) : "f"(x));
    return r;
}
__device__ __forceinline__ void cvt_hl(float v, uint32_t& h, uint32_t& l) {
    h = f2tf(v);
    float lo = v - __uint_as_float(h);
    l = f2tf(lo);
}
__device__ __forceinline__ void mma_tf32(float (&d)[4], const uint32_t (&a)[4], const uint32_t (&b)[2]) {
    asm volatile(
        "mma.sync.aligned.m16n8k8.row.col.f32.tf32.tf32.f32 "
        "{%0,%1,%2,%3}, {%4,%5,%6,%7}, {%8,%9}, {%0,%1,%2,%3};"
        : "+f"(d[0]), "+f"(d[1]), "+f"(d[2]), "+f"(d[3])
        : "r"(a[0]), "r"(a[1]), "r"(a[2]), "r"(a[3]), "r"(b[0]), "r"(b[1]));
}

// ---------------- length-descending schedule ----------------
__global__ void sort_order(const int* __restrict__ lengths, int* __restrict__ order)
{
    __shared__ int ls[BN];
    int b = threadIdx.x;
    ls[b] = lengths[b];
    __syncthreads();
    int len = ls[b];
    int rank = 0;
#pragma unroll 8
    for (int j = 0; j < BN; j++) {
        int lj = ls[j];
        rank += (lj > len) || (lj == len && j < b);
    }
    order[rank] = b;
}

// ---------------- weight zero-padding: [400,K] -> [448,Kp] ----------------
__global__ void pad_w(const float* __restrict__ src, float* __restrict__ dst,
                      int K, int Kp)
{
    int idx = blockIdx.x * 256 + threadIdx.x;
    int total = G4P * Kp;
    if (idx >= total) return;
    int r = idx / Kp, k = idx % Kp;
    dst[idx] = (r < G4 && k < K) ? src[r * K + k] : 0.f;
}

// ---------------- 3xTF32 tensor-core GEMM ----------------
// C[m,n] = sum_k A[m,k]*Bp[n,k] + bias1[n] + bias2[n],  N fixed = 400.
// CTA tile 128x64, BK=16, 256 threads = 8 warps (4m x 2n), warp tile 32x32.
// SKIP=1: rows indexed through elist (batch elements of this half);
//         blockIdx.y = elem*4 + tile;  skip tile if t0 >= lengths[b].
template<int SKIP>
__global__ void __launch_bounds__(256)
gemm_tf32(const float* __restrict__ A, int M, int Ks, int Kreal,
          const float* __restrict__ Bp, int Kp,
          const float* __restrict__ bias1, const float* __restrict__ bias2,
          const int* __restrict__ lengths, const int* __restrict__ elist,
          float* __restrict__ C)
{
    const int N = G4;
    int m0;
    const int n0 = blockIdx.x * 64;
    if (SKIP) {
        int b  = elist[blockIdx.y >> 2];
        int t0 = (blockIdx.y & 3) * 128;
        if (t0 >= lengths[b]) return;
        m0 = b * TN + t0;
    } else {
        m0 = blockIdx.y * 128;
    }

    __shared__ uint32_t As_hi[128 * 20], As_lo[128 * 20];
    __shared__ uint32_t Bs_hi[64 * 20],  Bs_lo[64 * 20];
    __shared__ float bias_s[64];

    const int tid  = threadIdx.x;
    const int wid  = tid >> 5;
    const int lane = tid & 31;
    const int wm   = wid & 3;
    const int wn   = wid >> 2;
    const int gid  = lane >> 2;
    const int tq   = lane & 3;

    if (tid < 64) {
        int n = n0 + tid;
        bias_s[tid] = (n < N) ? bias1[n] + bias2[n] : 0.f;
    }

    int mA[2], kqA[2];
#pragma unroll
    for (int i = 0; i < 2; i++) { int f = i * 256 + tid; mA[i] = f >> 2; kqA[i] = (f & 3) * 4; }
    const int nB = tid >> 2, kqB = (tid & 3) * 4;

    const float* aP[2];
#pragma unroll
    for (int i = 0; i < 2; i++) {
        int mg = m0 + mA[i]; if (mg > M - 1) mg = M - 1;
        aP[i] = A + (size_t)mg * Ks;
    }
    const float* bP = Bp + (size_t)(n0 + nB) * Kp;

    float acc[2][4][4];
#pragma unroll
    for (int i = 0; i < 2; i++)
#pragma unroll
        for (int j = 0; j < 4; j++)
#pragma unroll
            for (int q = 0; q < 4; q++) acc[i][j][q] = 0.f;

    const int kcl = Kreal - 4;
    float4 ra[2], rb;
#pragma unroll
    for (int i = 0; i < 2; i++) {
        int kk = kqA[i]; if (kk > kcl) kk = kcl;
        ra[i] = *reinterpret_cast<const float4*>(aP[i] + kk);
    }
    rb = *reinterpret_cast<const float4*>(bP + kqB);

    for (int k0 = 0; k0 < Kp; k0 += 16) {
#pragma unroll
        for (int i = 0; i < 2; i++) {
            uint32_t h0, l0, h1, l1, h2, l2, h3, l3;
            cvt_hl(ra[i].x, h0, l0); cvt_hl(ra[i].y, h1, l1);
            cvt_hl(ra[i].z, h2, l2); cvt_hl(ra[i].w, h3, l3);
            int off = mA[i] * 20 + kqA[i];
            *reinterpret_cast<uint4*>(&As_hi[off]) = make_uint4(h0, h1, h2, h3);
            *reinterpret_cast<uint4*>(&As_lo[off]) = make_uint4(l0, l1, l2, l3);
        }
        {
            uint32_t h0, l0, h1, l1, h2, l2, h3, l3;
            cvt_hl(rb.x, h0, l0); cvt_hl(rb.y, h1, l1);
            cvt_hl(rb.z, h2, l2); cvt_hl(rb.w, h3, l3);
            int off = nB * 20 + kqB;
            *reinterpret_cast<uint4*>(&Bs_hi[off]) = make_uint4(h0, h1, h2, h3);
            *reinterpret_cast<uint4*>(&Bs_lo[off]) = make_uint4(l0, l1, l2, l3);
        }
        __syncthreads();

        int k0n = k0 + 16;
        if (k0n < Kp) {
#pragma unroll
            for (int i = 0; i < 2; i++) {
                int kk = k0n + kqA[i]; if (kk > kcl) kk = kcl;
                ra[i] = *reinterpret_cast<const float4*>(aP[i] + kk);
            }
            rb = *reinterpret_cast<const float4*>(bP + k0n + kqB);
        }

#pragma unroll
        for (int ks = 0; ks < 2; ks++) {
            const int kb = ks * 8;
            uint32_t ah[2][4], al[2][4];
#pragma unroll
            for (int mf = 0; mf < 2; mf++) {
                int base = (wm * 32 + mf * 16 + gid) * 20 + kb + tq;
                ah[mf][0] = As_hi[base];              al[mf][0] = As_lo[base];
                ah[mf][1] = As_hi[base + 8 * 20];     al[mf][1] = As_lo[base + 8 * 20];
                ah[mf][2] = As_hi[base + 4];          al[mf][2] = As_lo[base + 4];
                ah[mf][3] = As_hi[base + 8 * 20 + 4]; al[mf][3] = As_lo[base + 8 * 20 + 4];
            }
            uint32_t bh[4][2], bl[4][2];
#pragma unroll
            for (int nf = 0; nf < 4; nf++) {
                int base = (wn * 32 + nf * 8 + gid) * 20 + kb + tq;
                bh[nf][0] = Bs_hi[base];     bl[nf][0] = Bs_lo[base];
                bh[nf][1] = Bs_hi[base + 4]; bl[nf][1] = Bs_lo[base + 4];
            }
#pragma unroll
            for (int mf = 0; mf < 2; mf++)
#pragma unroll
                for (int nf = 0; nf < 4; nf++) {
                    mma_tf32(acc[mf][nf], ah[mf], bh[nf]);
                    mma_tf32(acc[mf][nf], ah[mf], bl[nf]);
                    mma_tf32(acc[mf][nf], al[mf], bh[nf]);
                }
        }
        __syncthreads();
    }

#pragma unroll
    for (int mf = 0; mf < 2; mf++) {
#pragma unroll
        for (int nf = 0; nf < 4; nf++) {
            int row0 = m0 + wm * 32 + mf * 16 + gid;
            int cb   = wn * 32 + nf * 8 + 2 * tq;
            int col  = n0 + cb;
            if (col < N) {
                float b0v = bias_s[cb], b1v = bias_s[cb + 1];
                if (row0 < M) {
                    float2 v = make_float2(acc[mf][nf][0] + b0v, acc[mf][nf][1] + b1v);
                    *reinterpret_cast<float2*>(&C[(size_t)row0 * N + col]) = v;
                }
                int row1 = row0 + 8;
                if (row1 < M) {
                    float2 v = make_float2(acc[mf][nf][2] + b0v, acc[mf][nf][3] + b1v);
                    *reinterpret_cast<float2*>(&C[(size_t)row1 * N + col]) = v;
                }
            }
        }
    }
}

// ---------------- LSTM scan (quad-per-hidden-unit, 4 fma2 chains) ----------------
__device__ __forceinline__ float tanh_(float x) { return 2.f / (1.f + __expf(-2.f * x)) - 1.f; }

// thread tid = j*4 + g : hidden unit j (0..99), gate g (0=i,1=f,2=g,3=o)
// order_part points at this half's slice of the sorted order (HALF entries).
template<int MODE>
__global__ void __launch_bounds__(400, 1)
lstm_scan(const float* __restrict__ xg,
          const int* __restrict__ xtok,
          const int* __restrict__ lengths,
          const int* __restrict__ order_part,
          const float* __restrict__ w_hh,     // [400,100]
          float* __restrict__ h_out,          // [B,T,100]
          float* __restrict__ hlast)          // [B,100]
{
    const int b   = order_part[blockIdx.x];
    const int tid = threadIdx.x;
    const int j   = tid >> 2;
    const int g   = tid & 3;
    const int r   = g * 100 + j;

    __shared__ __align__(16) float h_s[2][104];
    __shared__ int idx_s[TN];

    const int len = lengths[b];

    if (MODE == 0) {
        for (int t = tid; t < TN; t += 400) idx_s[t] = xtok[b * TN + t];
    }

    ull w2[50];
    {
        const ull* wrow = reinterpret_cast<const ull*>(w_hh + r * 100);
#pragma unroll
        for (int q = 0; q < 50; q++) w2[q] = wrow[q];
    }

    if (tid < 100) h_s[0][tid] = 0.f;
    float c = 0.f;
    __syncthreads();

    const bool is_t = (g == 2);
    const bool gsel = (g & 2) != 0;

    float xg_next;
    if (MODE == 0) xg_next = xg[(size_t)idx_s[0] * G4 + r];
    else           xg_next = xg[((size_t)b * TN) * G4 + r];

    for (int t = 0; t < len; t++) {
        float xv = xg_next;
        if (t + 1 < len) {
            if (MODE == 0) xg_next = xg[(size_t)idx_s[t + 1] * G4 + r];
            else           xg_next = xg[((size_t)b * TN + t + 1) * G4 + r];
        }
        const ulonglong2* h2 = reinterpret_cast<const ulonglong2*>(h_s[t & 1]);

        // 4 independent fma2 chains (dep depth ~12-13)
        ull acc0 = pack2(xv, 0.f);
        ull acc1 = 0ULL, acc2v = 0ULL, acc3v = 0ULL;
#pragma unroll
        for (int q = 0; q < 12; q++) {
            ulonglong2 ha = h2[2 * q];
            ulonglong2 hb = h2[2 * q + 1];
            acc0  = fma2(ha.x, w2[4 * q],     acc0);
            acc1  = fma2(ha.y, w2[4 * q + 1], acc1);
            acc2v = fma2(hb.x, w2[4 * q + 2], acc2v);
            acc3v = fma2(hb.y, w2[4 * q + 3], acc3v);
        }
        {
            ulonglong2 ha = h2[24];
            acc0 = fma2(ha.x, w2[48], acc0);
            acc1 = fma2(ha.y, w2[49], acc1);
        }
        float a0, a1, a2, a3, a4, a5, a6, a7;
        unpack2(acc0, a0, a1);
        unpack2(acc1, a2, a3);
        unpack2(acc2v, a4, a5);
        unpack2(acc3v, a6, a7);
        float acc = ((a0 + a1) + (a2 + a3)) + ((a4 + a5) + (a6 + a7));

        float z = is_t ? 2.f * acc : acc;
        float s = 1.f / (1.f + __expf(-z));
        float gate = is_t ? (2.f * s - 1.f) : s;

        float v1 = __shfl_xor_sync(0xFFFFFFFFu, gate, 1);
        float pa = (g & 1) ? v1 : gate;
        float pb = (g & 1) ? gate : v1;
        float qa = __shfl_xor_sync(0xFFFFFFFFu, pa, 2);
        float qb = __shfl_xor_sync(0xFFFFFFFFu, pb, 2);
        float ig = gsel ? qa : pa;
        float gg = gsel ? pa : qa;
        float fg = gsel ? qb : pb;
        float og = gsel ? pb : qb;

        c = fg * c + ig * gg;
        float hn = og * tanh_(c);
        if (g == 0) {
            h_s[(t + 1) & 1][j] = hn;
            if (MODE != 2) h_out[((size_t)b * TN + t) * HN + j] = hn;
        }
        if (MODE == 2 && g == 0 && t == len - 1) hlast[b * HN + j] = hn;
        __syncthreads();
    }
}

// ---------------- head ----------------
__global__ void head_kernel(const float* __restrict__ hlast,
                            const float* __restrict__ w_fc,
                            const float* __restrict__ b_fc,
                            float* __restrict__ out)
{
    int b = blockIdx.x * blockDim.x + threadIdx.x;
    if (b >= BN) return;
#pragma unroll
    for (int o = 0; o < OUTN; o++) {
        float s = b_fc[o];
#pragma unroll
        for (int k = 0; k < HN; k++)
            s += hlast[b * HN + k] * w_fc[o * HN + k];
        out[b * OUTN + o] = s;
    }
}

// ---------------- launch (fork-join pipeline over two batch halves) ----------------
extern "C" void kernel_launch(void* const* d_in, const int* in_sizes, int n_in,
                              void* d_out, int out_size)
{
    const int*   x      = (const int*)d_in[0];
    const int*   lens   = (const int*)d_in[1];
    const float* emb    = (const float*)d_in[2];
    const float* w_ih0  = (const float*)d_in[3];
    const float* w_hh0  = (const float*)d_in[4];
    const float* b_ih0  = (const float*)d_in[5];
    const float* b_hh0  = (const float*)d_in[6];
    const float* w_ih1  = (const float*)d_in[7];
    const float* w_hh1  = (const float*)d_in[8];
    const float* b_ih1  = (const float*)d_in[9];
    const float* b_hh1  = (const float*)d_in[10];
    const float* w_ih2  = (const float*)d_in[11];
    const float* w_hh2  = (const float*)d_in[12];
    const float* b_ih2  = (const float*)d_in[13];
    const float* b_hh2  = (const float*)d_in[14];
    const float* w_fc   = (const float*)d_in[15];
    const float* b_fc   = (const float*)d_in[16];
    float* out = (float*)d_out;

    void *p_table, *p_xg, *p_h, *p_hlast, *p_order, *p_w0, *p_w1, *p_w2;
    cudaGetSymbolAddress(&p_table, g_table);
    cudaGetSymbolAddress(&p_xg,    g_xg);
    cudaGetSymbolAddress(&p_h,     g_h);
    cudaGetSymbolAddress(&p_hlast, g_hlast);
    cudaGetSymbolAddress(&p_order, g_order);
    cudaGetSymbolAddress(&p_w0,    g_w0p);
    cudaGetSymbolAddress(&p_w1,    g_w1p);
    cudaGetSymbolAddress(&p_w2,    g_w2p);
    float* table = (float*)p_table;
    float* xg    = (float*)p_xg;
    float* h     = (float*)p_h;
    float* hlast = (float*)p_hlast;
    int*   order = (int*)p_order;
    float* w0p   = (float*)p_w0;
    float* w1p   = (float*)p_w1;
    float* w2p   = (float*)p_w2;

    const int M = BN * TN;

    // one-time stream/event resources (no device memory involved)
    static cudaStream_t s1 = nullptr;
    static cudaEvent_t ev_fork = nullptr, ev_join = nullptr;
    if (!s1) {
        cudaStreamCreateWithFlags(&s1, cudaStreamNonBlocking);
        cudaEventCreateWithFlags(&ev_fork, cudaEventDisableTiming);
        cudaEventCreateWithFlags(&ev_join, cudaEventDisableTiming);
    }

    // ---- prologue (stream 0) ----
    sort_order<<<1, BN>>>(lens, order);
    pad_w<<<(G4P * KP0 + 255) / 256, 256>>>(w_ih0, w0p, DIMN, KP0);
    pad_w<<<(G4P * KP1 + 255) / 256, 256>>>(w_ih1, w1p, HN, KP1);
    pad_w<<<(G4P * KP1 + 255) / 256, 256>>>(w_ih2, w2p, HN, KP1);

    // table = emb @ w_ih0^T + b_ih0 + b_hh0
    {
        dim3 grid(7, (VOCABN + 127) / 128);
        gemm_tf32<0><<<grid, 256>>>(emb, VOCABN, DIMN, DIMN, w0p, KP0,
                                    b_ih0, b_hh0, nullptr, nullptr, table);
    }

    // ---- fork: H1 (short half) on side stream ----
    cudaEventRecord(ev_fork, 0);
    cudaStreamWaitEvent(s1, ev_fork, 0);

    const dim3 gskip(7, HALF * 4);

    // H0 (long half) chain on stream 0
    lstm_scan<0><<<HALF, 400>>>(table, x, lens, order, w_hh0, h, nullptr);
    gemm_tf32<1><<<gskip, 256>>>(h, M, HN, HN, w1p, KP1, b_ih1, b_hh1, lens, order, xg);
    lstm_scan<1><<<HALF, 400>>>(xg, nullptr, lens, order, w_hh1, h, nullptr);
    gemm_tf32<1><<<gskip, 256>>>(h, M, HN, HN, w2p, KP1, b_ih2, b_hh2, lens, order, xg);
    lstm_scan<2><<<HALF, 400>>>(xg, nullptr, lens, order, w_hh2, nullptr, hlast);

    // H1 (short half) chain on s1
    lstm_scan<0><<<HALF, 400, 0, s1>>>(table, x, lens, order + HALF, w_hh0, h, nullptr);
    gemm_tf32<1><<<gskip, 256, 0, s1>>>(h, M, HN, HN, w1p, KP1, b_ih1, b_hh1, lens, order + HALF, xg);
    lstm_scan<1><<<HALF, 400, 0, s1>>>(xg, nullptr, lens, order + HALF, w_hh1, h, nullptr);
    gemm_tf32<1><<<gskip, 256, 0, s1>>>(h, M, HN, HN, w2p, KP1, b_ih2, b_hh2, lens, order + HALF, xg);
    lstm_scan<2><<<HALF, 400, 0, s1>>>(xg, nullptr, lens, order + HALF, w_hh2, nullptr, hlast);

    // ---- join + head ----
    cudaEventRecord(ev_join, s1);
    cudaStreamWaitEvent(0, ev_join, 0);
    head_kernel<<<1, 256>>>(hlast, w_fc, b_fc, out);
}

// round 7
// speedup vs baseline: 1.0402x; 1.0402x over previous
#include <cuda_runtime.h>
#include <cstddef>
#include <cstdint>

#define VOCABN 50000
#define DIMN   300
#define HN     100
#define TN     512
#define BN     256
#define OUTN   3
#define G4     400   // 4*H
#define G4P    448   // padded N (7 tiles of 64)
#define KP0    304   // padded K for layer-0 table GEMM (emb K=300)
#define KP1    112   // padded K for xg GEMMs (h K=100)

// ---------------- scratch (static device globals; no allocation) ----------------
__device__ float g_table[(size_t)VOCABN * G4];
__device__ float g_xg[(size_t)BN * TN * G4];
__device__ float g_h[(size_t)BN * TN * HN];
__device__ float g_hlast[BN * HN];
__device__ int   g_order[BN];
__device__ float g_w0p[(size_t)G4P * KP0];
__device__ float g_w1p[(size_t)G4P * KP1];
__device__ float g_w2p[(size_t)G4P * KP1];

// ---------------- packed f32x2 helpers ----------------
typedef unsigned long long ull;

__device__ __forceinline__ ull pack2(float x, float y) {
    ull r;
    asm("mov.b64 %0, {%1, %2};" : "=l"(r) : "f"(x), "f"(y));
    return r;
}
__device__ __forceinline__ void unpack2(ull v, float& x, float& y) {
    asm("mov.b64 {%0, %1}, %2;" : "=f"(x), "=f"(y) : "l"(v));
}
__device__ __forceinline__ ull fma2(ull a, ull b, ull c) {
    ull d;
    asm("fma.rn.f32x2 %0, %1, %2, %3;" : "=l"(d) : "l"(a), "l"(b), "l"(c));
    return d;
}

// ---------------- tf32 helpers ----------------
__device__ __forceinline__ uint32_t f2tf(float x) {
    uint32_t r;
    asm("cvt.rna.tf32.f32 %0, %1;" : "=r"(r) : "f"(x));
    return r;
}
__device__ __forceinline__ void cvt_hl(float v, uint32_t& h, uint32_t& l) {
    h = f2tf(v);
    float lo = v - __uint_as_float(h);
    l = f2tf(lo);
}
__device__ __forceinline__ void mma_tf32(float (&d)[4], const uint32_t (&a)[4], const uint32_t (&b)[2]) {
    asm volatile(
        "mma.sync.aligned.m16n8k8.row.col.f32.tf32.tf32.f32 "
        "{%0,%1,%2,%3}, {%4,%5,%6,%7}, {%8,%9}, {%0,%1,%2,%3};"
        : "+f"(d[0]), "+f"(d[1]), "+f"(d[2]), "+f"(d[3])
        : "r"(a[0]), "r"(a[1]), "r"(a[2]), "r"(a[3]), "r"(b[0]), "r"(b[1]));
}

// ---------------- length-descending schedule ----------------
__global__ void sort_order(const int* __restrict__ lengths, int* __restrict__ order)
{
    __shared__ int ls[BN];
    int b = threadIdx.x;
    ls[b] = lengths[b];
    __syncthreads();
    int len = ls[b];
    int rank = 0;
#pragma unroll 8
    for (int j = 0; j < BN; j++) {
        int lj = ls[j];
        rank += (lj > len) || (lj == len && j < b);
    }
    order[rank] = b;
}

// ---------------- weight zero-padding: [400,K] -> [448,Kp] ----------------
__global__ void pad_w(const float* __restrict__ src, float* __restrict__ dst,
                      int K, int Kp)
{
    int idx = blockIdx.x * 256 + threadIdx.x;
    int total = G4P * Kp;
    if (idx >= total) return;
    int r = idx / Kp, k = idx % Kp;
    dst[idx] = (r < G4 && k < K) ? src[r * K + k] : 0.f;
}

// ---------------- 3xTF32 tensor-core GEMM (round-5, known good) ----------------
template<int SKIP>
__global__ void __launch_bounds__(256)
gemm_tf32(const float* __restrict__ A, int M, int Ks, int Kreal,
          const float* __restrict__ Bp, int Kp,
          const float* __restrict__ bias1, const float* __restrict__ bias2,
          const int* __restrict__ lengths, float* __restrict__ C)
{
    const int N = G4;
    const int m0 = blockIdx.y * 128;
    const int n0 = blockIdx.x * 64;
    if (SKIP) {
        int b  = m0 / TN;
        int t0 = m0 % TN;
        if (t0 >= lengths[b]) return;
    }

    __shared__ uint32_t As_hi[128 * 20], As_lo[128 * 20];
    __shared__ uint32_t Bs_hi[64 * 20],  Bs_lo[64 * 20];
    __shared__ float bias_s[64];

    const int tid  = threadIdx.x;
    const int wid  = tid >> 5;
    const int lane = tid & 31;
    const int wm   = wid & 3;
    const int wn   = wid >> 2;
    const int gid  = lane >> 2;
    const int tq   = lane & 3;

    if (tid < 64) {
        int n = n0 + tid;
        bias_s[tid] = (n < N) ? bias1[n] + bias2[n] : 0.f;
    }

    int mA[2], kqA[2];
#pragma unroll
    for (int i = 0; i < 2; i++) { int f = i * 256 + tid; mA[i] = f >> 2; kqA[i] = (f & 3) * 4; }
    const int nB = tid >> 2, kqB = (tid & 3) * 4;

    const float* aP[2];
#pragma unroll
    for (int i = 0; i < 2; i++) {
        int mg = m0 + mA[i]; if (mg > M - 1) mg = M - 1;
        aP[i] = A + (size_t)mg * Ks;
    }
    const float* bP = Bp + (size_t)(n0 + nB) * Kp;

    float acc[2][4][4];
#pragma unroll
    for (int i = 0; i < 2; i++)
#pragma unroll
        for (int j = 0; j < 4; j++)
#pragma unroll
            for (int q = 0; q < 4; q++) acc[i][j][q] = 0.f;

    const int kcl = Kreal - 4;
    float4 ra[2], rb;
#pragma unroll
    for (int i = 0; i < 2; i++) {
        int kk = kqA[i]; if (kk > kcl) kk = kcl;
        ra[i] = *reinterpret_cast<const float4*>(aP[i] + kk);
    }
    rb = *reinterpret_cast<const float4*>(bP + kqB);

    for (int k0 = 0; k0 < Kp; k0 += 16) {
#pragma unroll
        for (int i = 0; i < 2; i++) {
            uint32_t h0, l0, h1, l1, h2, l2, h3, l3;
            cvt_hl(ra[i].x, h0, l0); cvt_hl(ra[i].y, h1, l1);
            cvt_hl(ra[i].z, h2, l2); cvt_hl(ra[i].w, h3, l3);
            int off = mA[i] * 20 + kqA[i];
            *reinterpret_cast<uint4*>(&As_hi[off]) = make_uint4(h0, h1, h2, h3);
            *reinterpret_cast<uint4*>(&As_lo[off]) = make_uint4(l0, l1, l2, l3);
        }
        {
            uint32_t h0, l0, h1, l1, h2, l2, h3, l3;
            cvt_hl(rb.x, h0, l0); cvt_hl(rb.y, h1, l1);
            cvt_hl(rb.z, h2, l2); cvt_hl(rb.w, h3, l3);
            int off = nB * 20 + kqB;
            *reinterpret_cast<uint4*>(&Bs_hi[off]) = make_uint4(h0, h1, h2, h3);
            *reinterpret_cast<uint4*>(&Bs_lo[off]) = make_uint4(l0, l1, l2, l3);
        }
        __syncthreads();

        int k0n = k0 + 16;
        if (k0n < Kp) {
#pragma unroll
            for (int i = 0; i < 2; i++) {
                int kk = k0n + kqA[i]; if (kk > kcl) kk = kcl;
                ra[i] = *reinterpret_cast<const float4*>(aP[i] + kk);
            }
            rb = *reinterpret_cast<const float4*>(bP + k0n + kqB);
        }

#pragma unroll
        for (int ks = 0; ks < 2; ks++) {
            const int kb = ks * 8;
            uint32_t ah[2][4], al[2][4];
#pragma unroll
            for (int mf = 0; mf < 2; mf++) {
                int base = (wm * 32 + mf * 16 + gid) * 20 + kb + tq;
                ah[mf][0] = As_hi[base];              al[mf][0] = As_lo[base];
                ah[mf][1] = As_hi[base + 8 * 20];     al[mf][1] = As_lo[base + 8 * 20];
                ah[mf][2] = As_hi[base + 4];          al[mf][2] = As_lo[base + 4];
                ah[mf][3] = As_hi[base + 8 * 20 + 4]; al[mf][3] = As_lo[base + 8 * 20 + 4];
            }
            uint32_t bh[4][2], bl[4][2];
#pragma unroll
            for (int nf = 0; nf < 4; nf++) {
                int base = (wn * 32 + nf * 8 + gid) * 20 + kb + tq;
                bh[nf][0] = Bs_hi[base];     bl[nf][0] = Bs_lo[base];
                bh[nf][1] = Bs_hi[base + 4]; bl[nf][1] = Bs_lo[base + 4];
            }
#pragma unroll
            for (int mf = 0; mf < 2; mf++)
#pragma unroll
                for (int nf = 0; nf < 4; nf++) {
                    mma_tf32(acc[mf][nf], ah[mf], bh[nf]);
                    mma_tf32(acc[mf][nf], ah[mf], bl[nf]);
                    mma_tf32(acc[mf][nf], al[mf], bh[nf]);
                }
        }
        __syncthreads();
    }

#pragma unroll
    for (int mf = 0; mf < 2; mf++) {
#pragma unroll
        for (int nf = 0; nf < 4; nf++) {
            int row0 = m0 + wm * 32 + mf * 16 + gid;
            int cb   = wn * 32 + nf * 8 + 2 * tq;
            int col  = n0 + cb;
            if (col < N) {
                float b0v = bias_s[cb], b1v = bias_s[cb + 1];
                if (row0 < M) {
                    float2 v = make_float2(acc[mf][nf][0] + b0v, acc[mf][nf][1] + b1v);
                    *reinterpret_cast<float2*>(&C[(size_t)row0 * N + col]) = v;
                }
                int row1 = row0 + 8;
                if (row1 < M) {
                    float2 v = make_float2(acc[mf][nf][2] + b0v, acc[mf][nf][3] + b1v);
                    *reinterpret_cast<float2*>(&C[(size_t)row1 * N + col]) = v;
                }
            }
        }
    }
}

// ---------------- LSTM scan (chunk-split matvec, 1 element / CTA) ----------------
__device__ __forceinline__ float tanh_(float x) { return 2.f / (1.f + __expf(-2.f * x)) - 1.f; }

// select s[g^X] from 4 scalar regs without dynamic indexing
__device__ __forceinline__ float sel0(int g, float s0, float s1, float s2, float s3) {
    return (g & 1) ? ((g & 2) ? s3 : s1) : ((g & 2) ? s2 : s0);
}
__device__ __forceinline__ float sel1(int g, float s0, float s1, float s2, float s3) {
    return (g & 1) ? ((g & 2) ? s2 : s0) : ((g & 2) ? s3 : s1);
}
__device__ __forceinline__ float sel2(int g, float s0, float s1, float s2, float s3) {
    return (g & 1) ? ((g & 2) ? s1 : s3) : ((g & 2) ? s0 : s2);
}
__device__ __forceinline__ float sel3(int g, float s0, float s1, float s2, float s3) {
    return (g & 1) ? ((g & 2) ? s0 : s2) : ((g & 2) ? s1 : s3);
}

// quad transpose-reduce: lane g of each quad returns sum over all 4 chunks of gate g
__device__ __forceinline__ float quad_reduce(unsigned mask, int g,
                                             float s0, float s1, float s2, float s3)
{
    float r1 = __shfl_xor_sync(mask, sel1(g, s0, s1, s2, s3), 1);
    float u1 = sel0(g, s0, s1, s2, s3) + r1;
    float r2 = __shfl_xor_sync(mask, sel3(g, s0, s1, s2, s3), 1);
    float u2 = sel2(g, s0, s1, s2, s3) + r2;
    float r3 = __shfl_xor_sync(mask, u2, 2);
    return u1 + r3;
}

// thread tid = j*4 + g : hidden unit j (0..99), lane-role g (chunk & gate id).
// Lane (j,g) holds, for all 4 gate rows of unit j, h-chunk g of the weights.
template<int MODE>
__global__ void __launch_bounds__(400, 1)
lstm_scan(const float* __restrict__ xg,
          const int* __restrict__ xtok,
          const int* __restrict__ lengths,
          const int* __restrict__ order,
          const float* __restrict__ w_hh,     // [400,100]
          float* __restrict__ h_out,          // [B,T,100]
          float* __restrict__ hlast)          // [B,100]
{
    const int b   = order[blockIdx.x];
    const int tid = threadIdx.x;
    const int j   = tid >> 2;
    const int g   = tid & 3;
    const int r   = g * 100 + j;               // this lane's own gate row (for xg)
    const unsigned mask = (tid >= 384) ? 0xFFFFu : 0xFFFFFFFFu;

    // h state: chunk layout with pitch 28; chunk c holds h[c*25 .. c*25+24]
    __shared__ __align__(16) float h_s[2][4 * 28];
    __shared__ int idx_s[TN];

    const int len = lengths[b];

    if (MODE == 0) {
        for (int t = tid; t < TN; t += 400) idx_s[t] = xtok[b * TN + t];
    }

    // weights: for gate row gp of unit j, chunk g (25 floats = 12 pairs + tail)
    ull   wp[4][12];
    float wl[4];
#pragma unroll
    for (int gp = 0; gp < 4; gp++) {
        const float* wr = w_hh + (size_t)(gp * 100 + j) * 100 + g * 25;
#pragma unroll
        for (int q = 0; q < 12; q++) wp[gp][q] = pack2(wr[2 * q], wr[2 * q + 1]);
        wl[gp] = wr[24];
    }

    const int jc = (j / 25) * 28 + (j % 25);   // smem slot of unit j
    if (g == 0) h_s[0][jc] = 0.f;
    float c = 0.f, hk = 0.f;
    __syncthreads();

    const bool is_t = (g == 2);
    const bool gsel = (g & 2) != 0;

    float xg_next;
    if (MODE == 0) xg_next = xg[(size_t)idx_s[0] * G4 + r];
    else           xg_next = xg[((size_t)b * TN) * G4 + r];

    for (int t = 0; t < len; t++) {
        float xv = xg_next;
        if (t + 1 < len) {
            if (MODE == 0) xg_next = xg[(size_t)idx_s[t + 1] * G4 + r];
            else           xg_next = xg[((size_t)b * TN + t + 1) * G4 + r];
        }

        // chunk matvec: 4 gate-partials over this lane's 25 h values
        const float* hc = &h_s[t & 1][g * 28];
        const ull* h2 = reinterpret_cast<const ull*>(hc);
        ull a0 = 0ULL, a1 = 0ULL, a2v = 0ULL, a3v = 0ULL;
#pragma unroll
        for (int q = 0; q < 12; q++) {
            ull hh = h2[q];
            a0  = fma2(hh, wp[0][q], a0);
            a1  = fma2(hh, wp[1][q], a1);
            a2v = fma2(hh, wp[2][q], a2v);
            a3v = fma2(hh, wp[3][q], a3v);
        }
        float hl = hc[24];
        float lo, hi;
        float s0, s1, s2, s3;
        unpack2(a0,  lo, hi); s0 = lo + hi + hl * wl[0];
        unpack2(a1,  lo, hi); s1 = lo + hi + hl * wl[1];
        unpack2(a2v, lo, hi); s2 = lo + hi + hl * wl[2];
        unpack2(a3v, lo, hi); s3 = lo + hi + hl * wl[3];

        float acc = quad_reduce(mask, g, s0, s1, s2, s3) + xv;

        // activation (sigmoid for g=0,1,3; tanh for g=2), divergence-free
        float z = is_t ? 2.f * acc : acc;
        float e = 1.f / (1.f + __expf(-z));
        float gate = is_t ? (2.f * e - 1.f) : e;

        // quad exchange: collect i,f,g,o in every lane
        float v1 = __shfl_xor_sync(mask, gate, 1);
        float pa = (g & 1) ? v1 : gate;
        float pb = (g & 1) ? gate : v1;
        float qa = __shfl_xor_sync(mask, pa, 2);
        float qb = __shfl_xor_sync(mask, pb, 2);
        float ig = gsel ? qa : pa;
        float gg = gsel ? pa : qa;
        float fg = gsel ? qb : pb;
        float og = gsel ? pb : qb;

        c = fg * c + ig * gg;
        float hn = og * tanh_(c);
        if (g == 0) {
            h_s[(t + 1) & 1][jc] = hn;
            if (MODE != 2) h_out[((size_t)b * TN + t) * HN + j] = hn;
        }
        if (MODE == 2 && g == 0 && t == len - 1) hlast[b * HN + j] = hn;
        __syncthreads();
    }
}

// ---------------- head ----------------
__global__ void head_kernel(const float* __restrict__ hlast,
                            const float* __restrict__ w_fc,
                            const float* __restrict__ b_fc,
                            float* __restrict__ out)
{
    int b = blockIdx.x * blockDim.x + threadIdx.x;
    if (b >= BN) return;
#pragma unroll
    for (int o = 0; o < OUTN; o++) {
        float s = b_fc[o];
#pragma unroll
        for (int k = 0; k < HN; k++)
            s += hlast[b * HN + k] * w_fc[o * HN + k];
        out[b * OUTN + o] = s;
    }
}

// ---------------- launch (single stream, round-5 schedule) ----------------
extern "C" void kernel_launch(void* const* d_in, const int* in_sizes, int n_in,
                              void* d_out, int out_size)
{
    const int*   x      = (const int*)d_in[0];
    const int*   lens   = (const int*)d_in[1];
    const float* emb    = (const float*)d_in[2];
    const float* w_ih0  = (const float*)d_in[3];
    const float* w_hh0  = (const float*)d_in[4];
    const float* b_ih0  = (const float*)d_in[5];
    const float* b_hh0  = (const float*)d_in[6];
    const float* w_ih1  = (const float*)d_in[7];
    const float* w_hh1  = (const float*)d_in[8];
    const float* b_ih1  = (const float*)d_in[9];
    const float* b_hh1  = (const float*)d_in[10];
    const float* w_ih2  = (const float*)d_in[11];
    const float* w_hh2  = (const float*)d_in[12];
    const float* b_ih2  = (const float*)d_in[13];
    const float* b_hh2  = (const float*)d_in[14];
    const float* w_fc   = (const float*)d_in[15];
    const float* b_fc   = (const float*)d_in[16];
    float* out = (float*)d_out;

    void *p_table, *p_xg, *p_h, *p_hlast, *p_order, *p_w0, *p_w1, *p_w2;
    cudaGetSymbolAddress(&p_table, g_table);
    cudaGetSymbolAddress(&p_xg,    g_xg);
    cudaGetSymbolAddress(&p_h,     g_h);
    cudaGetSymbolAddress(&p_hlast, g_hlast);
    cudaGetSymbolAddress(&p_order, g_order);
    cudaGetSymbolAddress(&p_w0,    g_w0p);
    cudaGetSymbolAddress(&p_w1,    g_w1p);
    cudaGetSymbolAddress(&p_w2,    g_w2p);
    float* table = (float*)p_table;
    float* xg    = (float*)p_xg;
    float* h     = (float*)p_h;
    float* hlast = (float*)p_hlast;
    int*   order = (int*)p_order;
    float* w0p   = (float*)p_w0;
    float* w1p   = (float*)p_w1;
    float* w2p   = (float*)p_w2;

    const int M = BN * TN;

    // 0) schedule + weight padding
    sort_order<<<1, BN>>>(lens, order);
    pad_w<<<(G4P * KP0 + 255) / 256, 256>>>(w_ih0, w0p, DIMN, KP0);
    pad_w<<<(G4P * KP1 + 255) / 256, 256>>>(w_ih1, w1p, HN, KP1);
    pad_w<<<(G4P * KP1 + 255) / 256, 256>>>(w_ih2, w2p, HN, KP1);

    // 1) vocab table GEMM: table = emb @ w_ih0^T + b_ih0 + b_hh0
    {
        dim3 grid(7, (VOCABN + 127) / 128);
        gemm_tf32<0><<<grid, 256>>>(emb, VOCABN, DIMN, DIMN, w0p, KP0,
                                    b_ih0, b_hh0, nullptr, table);
    }
    // 2) layer 0 scan (gathers table rows directly)
    lstm_scan<0><<<BN, 400>>>(table, x, lens, order, w_hh0, h, nullptr);

    // 3) layer 1 xg GEMM (+length tile-skip), then scan
    {
        dim3 grid(7, M / 128);
        gemm_tf32<1><<<grid, 256>>>(h, M, HN, HN, w1p, KP1,
                                    b_ih1, b_hh1, lens, xg);
    }
    lstm_scan<1><<<BN, 400>>>(xg, nullptr, lens, order, w_hh1, h, nullptr);

    // 4) layer 2 xg GEMM, then scan (hlast only)
    {
        dim3 grid(7, M / 128);
        gemm_tf32<1><<<grid, 256>>>(h, M, HN, HN, w2p, KP1,
                                    b_ih2, b_hh2, lens, xg);
    }
    lstm_scan<2><<<BN, 400>>>(xg, nullptr, lens, order, w_hh2, nullptr, hlast);

    // 5) head
    head_kernel<<<1, 256>>>(hlast, w_fc, b_fc, out);
}